// round 13
// baseline (speedup 1.0000x reference)
#include <cuda_runtime.h>
#include <cuda_fp16.h>
#include <cstdint>

// ---------------- problem constants ----------------
#define N_TOK 4096
#define D_IN  2048
#define D_OUT 2048
#define RANK  16
#define MAX_LORAS 32

// ---------------- GEMM tiling ----------------
#define BM 128
#define BN 64                 // finer tiles for load balance
#define BK 64                 // fp16 elems per K-tile (128 bytes/row)
#define NKT (D_IN / BK)       // 32
#define TPB 256
#define STAGES 3
#define NTILES ((N_TOK / BM) * (D_OUT / BN))   // 32 * 32 = 1024
#define GRID_PERSIST 304      // 2 CTAs/SM x 152 SMs (GB300)

#define A_ARR_BYTES (128 * 128)          // 16384 (A tile: 128 rows x 128B)
#define B_ARR_BYTES (64 * 128)           // 8192  (B tile: 64 rows x 128B)
#define STAGE_BYTES (A_ARR_BYTES + B_ARR_BYTES)   // 24576
#define DYN_BYTES (STAGES * STAGE_BYTES)          // 73728 -> 2 CTAs/SM

// XOR-SW128 swizzle: byte addr = row*128 + (col ^ ((row&7)<<4)), col in [0,128)
#define SWADDR(row, col) ((uint32_t)((row) * 128 + ((col) ^ (((row) & 7) << 4))))

// ---------------- device scratch (no runtime allocation allowed) ----------------
__device__ __align__(16) float  g_Ares[N_TOK * RANK];     // SORTED token order
__device__ __align__(16) __half g_Xi[N_TOK * D_IN];
__device__ __align__(16) __half g_Wi[D_OUT * D_IN];
__device__ __align__(16) __half g_Ai[MAX_LORAS * RANK * D_IN];
__device__ __align__(16) __half g_Bi[MAX_LORAS * D_OUT * RANK];
__device__ __align__(16) int    g_perm[N_TOK];            // sorted pos -> token
__device__ __align__(16) int    g_sortedAdp[N_TOK];       // sorted pos -> adapter
__device__ __align__(16) int    g_binStart[MAX_LORAS + 1];
__device__ unsigned int g_tileCtr;                        // reset by prepass

// ---------------- PTX helpers (baseline-portable: sm_80-era ops) ----------------
__device__ __forceinline__ uint32_t smem_u32(const void* p) {
    uint32_t a;
    asm("{ .reg .u64 t; cvta.to.shared.u64 t, %1; cvt.u32.u64 %0, t; }" : "=r"(a) : "l"(p));
    return a;
}
#define CP16(dst, src) \
    asm volatile("cp.async.cg.shared.global [%0], [%1], 16;" :: "r"(dst), "l"(src) : "memory")
#define CP_COMMIT()  asm volatile("cp.async.commit_group;" ::: "memory")
#define CP_WAIT(n)   asm volatile("cp.async.wait_group %0;" :: "n"(n) : "memory")

__device__ __forceinline__ void ldsm4(uint32_t* r, uint32_t addr) {
    asm volatile("ldmatrix.sync.aligned.m8n8.x4.shared.b16 {%0,%1,%2,%3}, [%4];"
        : "=r"(r[0]), "=r"(r[1]), "=r"(r[2]), "=r"(r[3]) : "r"(addr));
}
__device__ __forceinline__ void mma_f16(float* d, const uint32_t* a,
                                        uint32_t b0, uint32_t b1) {
    asm volatile(
        "mma.sync.aligned.m16n8k16.row.col.f32.f16.f16.f32 "
        "{%0,%1,%2,%3}, {%4,%5,%6,%7}, {%8,%9}, {%0,%1,%2,%3};"
        : "+f"(d[0]), "+f"(d[1]), "+f"(d[2]), "+f"(d[3])
        : "r"(a[0]), "r"(a[1]), "r"(a[2]), "r"(a[3]), "r"(b0), "r"(b1));
}
__device__ __forceinline__ float dot_h2(float acc, uint32_t h2, float a0, float a1) {
    float2 f = __half22float2(*reinterpret_cast<__half2*>(&h2));
    return acc + a0 * f.x + a1 * f.y;
}
__device__ __forceinline__ uint2 f4_to_h4(float4 v) {
    __half2 p0 = __floats2half2_rn(v.x, v.y);
    __half2 p1 = __floats2half2_rn(v.z, v.w);
    uint2 u;
    u.x = *reinterpret_cast<uint32_t*>(&p0);
    u.y = *reinterpret_cast<uint32_t*>(&p1);
    return u;
}

// ---------------------------------------------------------------------------
// Kernel 1 (prepass):
//   block 0:             sort (runs CONCURRENTLY with converts — fixes the
//                        serial tail of R12 where it was the LAST block)
//                        + tile-counter reset
//   blocks [1, 2049):    X convert, 4 float4/thread (2M float4 total)
//   blocks [2049, 3073): W convert, 4 float4/thread (1M float4 total)
//   blocks [3073, 4097): loraA + loraB convert
// ---------------------------------------------------------------------------
__global__ __launch_bounds__(256) void prepass_kernel(
    const float* __restrict__ x, const float* __restrict__ w,
    const float* __restrict__ lora_A, const float* __restrict__ lora_B,
    const int* __restrict__ adapter_ids)
{
    const int bid = blockIdx.x;
    const int tid = threadIdx.x;

    if (bid == 0) {
        // ---- stable counting sort of 4096 tokens into 32 bins ----
        __shared__ uint32_t hist[256 * 33];   // padded stride (bank spread)
        __shared__ uint32_t binTotal[32];
        __shared__ uint32_t binBase[33];

        if (tid == 0) g_tileCtr = 0u;         // persistent-GEMM counter reset

        int ids[16];
        #pragma unroll
        for (int j = 0; j < 33; j++) hist[tid * 33 + j] = 0;
        __syncthreads();
        #pragma unroll
        for (int j = 0; j < 16; j++) {
            ids[j] = adapter_ids[tid * 16 + j];
            hist[tid * 33 + ids[j]]++;
        }
        __syncthreads();
        if (tid < 32) {        // per-bin prefix over threads (stable base)
            uint32_t s = 0;
            for (int t = 0; t < 256; t++) {
                uint32_t c = hist[t * 33 + tid];
                hist[t * 33 + tid] = s;
                s += c;
            }
            binTotal[tid] = s;
        }
        __syncthreads();
        if (tid == 0) {
            uint32_t acc = 0;
            for (int b = 0; b < 32; b++) { binBase[b] = acc; acc += binTotal[b]; }
            binBase[32] = acc;   // = 4096
        }
        __syncthreads();
        #pragma unroll
        for (int j = 0; j < 16; j++) {       // stable scatter
            const int b = ids[j];
            const uint32_t off = hist[tid * 33 + b]++;
            const uint32_t pos = binBase[b] + off;
            g_perm[pos]      = tid * 16 + j;
            g_sortedAdp[pos] = b;
        }
        if (tid < 33) g_binStart[tid] = (int)binBase[tid];
        return;
    }

    if (bid < 2049) {                                // X: 2048 blocks, 2M float4
        const int base = (bid - 1) * 1024 + tid;
        float4 v0 = reinterpret_cast<const float4*>(x)[base + 0 * 256];
        float4 v1 = reinterpret_cast<const float4*>(x)[base + 1 * 256];
        float4 v2 = reinterpret_cast<const float4*>(x)[base + 2 * 256];
        float4 v3 = reinterpret_cast<const float4*>(x)[base + 3 * 256];
        *reinterpret_cast<uint2*>(&g_Xi[(size_t)(base + 0 * 256) * 4]) = f4_to_h4(v0);
        *reinterpret_cast<uint2*>(&g_Xi[(size_t)(base + 1 * 256) * 4]) = f4_to_h4(v1);
        *reinterpret_cast<uint2*>(&g_Xi[(size_t)(base + 2 * 256) * 4]) = f4_to_h4(v2);
        *reinterpret_cast<uint2*>(&g_Xi[(size_t)(base + 3 * 256) * 4]) = f4_to_h4(v3);
        return;
    }
    if (bid < 3073) {                                // W: 1024 blocks, 1M float4
        const int base = (bid - 2049) * 1024 + tid;
        float4 v0 = reinterpret_cast<const float4*>(w)[base + 0 * 256];
        float4 v1 = reinterpret_cast<const float4*>(w)[base + 1 * 256];
        float4 v2 = reinterpret_cast<const float4*>(w)[base + 2 * 256];
        float4 v3 = reinterpret_cast<const float4*>(w)[base + 3 * 256];
        *reinterpret_cast<uint2*>(&g_Wi[(size_t)(base + 0 * 256) * 4]) = f4_to_h4(v0);
        *reinterpret_cast<uint2*>(&g_Wi[(size_t)(base + 1 * 256) * 4]) = f4_to_h4(v1);
        *reinterpret_cast<uint2*>(&g_Wi[(size_t)(base + 2 * 256) * 4]) = f4_to_h4(v2);
        *reinterpret_cast<uint2*>(&g_Wi[(size_t)(base + 3 * 256) * 4]) = f4_to_h4(v3);
        return;
    }
    {                                                // loraA/B: 262144 f4 each
        const int idx = (bid - 3073) * 256 + tid;
        float4 va = reinterpret_cast<const float4*>(lora_A)[idx];
        float4 vb = reinterpret_cast<const float4*>(lora_B)[idx];
        *reinterpret_cast<uint2*>(&g_Ai[(size_t)idx * 4]) = f4_to_h4(va);
        *reinterpret_cast<uint2*>(&g_Bi[(size_t)idx * 4]) = f4_to_h4(vb);
    }
}

// ---------------------------------------------------------------------------
// Kernel 2: shrink as per-adapter mma GEMM (unchanged — proven).
// ---------------------------------------------------------------------------
__global__ __launch_bounds__(256) void shrink_gemm_kernel()
{
    __shared__ __align__(16) char xs[2][16384];   // X tiles 128x64 fp16
    __shared__ __align__(16) char as_[2][2048];   // A tiles 16x64 fp16
    __shared__ int tokSh[128];

    const int a   = blockIdx.x;
    const int cy  = blockIdx.y;
    const int tid = threadIdx.x;
    const int wid = tid >> 5, lane = tid & 31;

    const int binS = g_binStart[a], binE = g_binStart[a + 1];
    const int base = binS + cy * 128;
    int cnt = binE - base;
    if (cnt <= 0) return;
    if (cnt > 128) cnt = 128;

    if (tid < 128) tokSh[tid] = g_perm[base + (tid < cnt ? tid : cnt - 1)];
    __syncthreads();

    const int ldCol = (tid & 7) * 16;
    auto load = [&](int kt, int stg) {
        #pragma unroll
        for (int i = 0; i < 4; i++) {
            const int c = tid + i * 256;          // 0..1023
            const int row = c >> 3;
            CP16(smem_u32(xs[stg]) + SWADDR(row, ldCol),
                 (const char*)g_Xi + (size_t)tokSh[row] * 4096 + kt * 128 + ldCol);
        }
        if (tid < 128) {
            const int row = tid >> 3;             // 0..15
            CP16(smem_u32(as_[stg]) + SWADDR(row, ldCol),
                 (const char*)g_Ai + ((size_t)a * RANK + row) * 4096 + kt * 128 + ldCol);
        }
        CP_COMMIT();
    };

    float acc2[2][4];
    #pragma unroll
    for (int i = 0; i < 2; i++)
        #pragma unroll
        for (int k = 0; k < 4; k++) acc2[i][k] = 0.f;

    const int lmRow = lane & 15, lmChunk = (lane >> 4) * 16;

    load(0, 0);
    for (int kt = 0; kt < NKT; kt++) {
        if (kt + 1 < NKT) load(kt + 1, (kt + 1) & 1); else CP_COMMIT();
        CP_WAIT(1);
        __syncthreads();
        const uint32_t xb = smem_u32(xs[kt & 1]);
        const uint32_t ab = smem_u32(as_[kt & 1]);
        #pragma unroll
        for (int s = 0; s < 4; s++) {
            uint32_t xh[4], bh[4];
            ldsm4(xh, xb + SWADDR(wid * 16 + lmRow, s * 32 + lmChunk));
            ldsm4(bh, ab + SWADDR(lmRow,           s * 32 + lmChunk));
            mma_f16(acc2[0], xh, bh[0], bh[2]);
            mma_f16(acc2[1], xh, bh[1], bh[3]);
        }
        __syncthreads();   // protect stage (kt+1)&1 reuse next iteration
    }

    const int gID = lane >> 2, tig = lane & 3;
    #pragma unroll
    for (int h = 0; h < 2; h++) {
        const int r = wid * 16 + gID + h * 8;
        if (r < cnt) {
            float* dst = g_Ares + (size_t)(base + r) * RANK;
            #pragma unroll
            for (int ng = 0; ng < 2; ng++) {
                const int c = ng * 8 + 2 * tig;
                *reinterpret_cast<float2*>(dst + c) =
                    make_float2(acc2[ng][h * 2], acc2[ng][h * 2 + 1]);
            }
        }
    }
}

// ---------------------------------------------------------------------------
// Kernel 3: persistent fp16 mma.sync GEMM, BM=128 x BN=64 tiles with atomic
// work stealing (1024 tiles over 304 CTAs — fine-grained balance).
// 8 warps in 4x2: warp tile 32 rows x 32 cols. fp32 acc.
// Deterministic: tiles disjoint; per-tile math independent of worker.
// ---------------------------------------------------------------------------
__global__ __launch_bounds__(TPB, 2) void gemm_mma_kernel(
    const float* __restrict__ bias,
    const float* __restrict__ scaling,
    float*       __restrict__ out)
{
    extern __shared__ char dsm[];
    __shared__ __align__(16) float AresSh[BM][RANK];
    __shared__ int   adSh[BM];
    __shared__ float scSh[BM];
    __shared__ int   tokSh[BM];
    __shared__ unsigned int s_tile;

    const int tid  = threadIdx.x;
    const int wid  = tid >> 5, lane = tid & 31;
    const int warpM = wid >> 1;          // 0..3 (32 rows each)
    const int warpN = wid & 1;           // 0..1 (32 cols each)

    const uint32_t dynb = smem_u32(dsm);
    const int lmRow   = lane & 15;
    const int lmChunk = (lane >> 4) * 16;
    const int aRow0 = warpM * 32 + lmRow;
    const int bRow0 = warpN * 32 + lmRow;
    const int ldCol = (tid & 7) * 16;

    for (;;) {
        // fetch next tile; the barrier also closes the WAR window on the
        // preload arrays (prior epilogue readers have arrived).
        if (tid == 0) s_tile = atomicAdd(&g_tileCtr, 1u);
        __syncthreads();
        const unsigned int t = s_tile;
        if (t >= NTILES) break;

        const int rowBlock = (int)(t >> 5) * BM;     // 32 row groups
        const int colBlock = (int)(t & 31) * BN;     // 32 col groups of 64

        // preload: Ares rows (sorted-contiguous), adapters, scales, tokens
        {
            const float4* ag  = reinterpret_cast<const float4*>(g_Ares + (size_t)rowBlock * RANK);
            float4*       as4 = reinterpret_cast<float4*>(&AresSh[0][0]);
            as4[tid]       = ag[tid];
            as4[tid + 256] = ag[tid + 256];
            if (tid < BM) {
                const int sp = rowBlock + tid;
                const int a  = g_sortedAdp[sp];
                adSh[tid]  = a;
                scSh[tid]  = scaling[a];
                tokSh[tid] = g_perm[sp];
            }
        }
        __syncthreads();   // tokSh ready before gathered loads

        const char* srcW = (const char*)(g_Wi + (size_t)colBlock * D_IN);

        auto load_tile = [&](int kt, int stg) {
            const uint32_t sb = dynb + stg * STAGE_BYTES;
            const size_t koff = (size_t)kt * (BK * 2);   // 128 B per row
            // A: 1024 chunks (4/thread)
            #pragma unroll
            for (int i = 0; i < 4; i++) {
                const int c   = tid + i * 256;
                const int row = c >> 3;
                CP16(sb + SWADDR(row, ldCol),
                     (const char*)g_Xi + (size_t)tokSh[row] * (D_IN * 2) + koff + ldCol);
            }
            // B: 512 chunks (2/thread)
            #pragma unroll
            for (int i = 0; i < 2; i++) {
                const int c   = tid + i * 256;
                const int row = c >> 3;                   // 0..63
                CP16(sb + A_ARR_BYTES + SWADDR(row, ldCol),
                     srcW + (size_t)row * (D_IN * 2) + koff + ldCol);
            }
            CP_COMMIT();
        };

        float acc[2][4][4];
        #pragma unroll
        for (int m = 0; m < 2; m++)
            #pragma unroll
            for (int n = 0; n < 4; n++)
                #pragma unroll
                for (int k = 0; k < 4; k++) acc[m][n][k] = 0.f;

        load_tile(0, 0);
        load_tile(1, 1);

        for (int kt = 0; kt < NKT; kt++) {
            const int stg = kt % STAGES;
            CP_WAIT(STAGES - 2);
            __syncthreads();
            if (kt + STAGES - 1 < NKT)
                load_tile(kt + STAGES - 1, (kt + STAGES - 1) % STAGES);
            else
                CP_COMMIT();   // empty group keeps wait accounting exact

            const uint32_t sb = dynb + stg * STAGE_BYTES;
            const uint32_t aArr = sb;
            const uint32_t bArr = sb + A_ARR_BYTES;

            #pragma unroll
            for (int s = 0; s < 4; s++) {
                const int ko = s * 32;
                uint32_t ah[2][4], bh[2][4];
                #pragma unroll
                for (int m = 0; m < 2; m++)
                    ldsm4(ah[m], aArr + SWADDR(aRow0 + m * 16, ko + lmChunk));
                #pragma unroll
                for (int g = 0; g < 2; g++)
                    ldsm4(bh[g], bArr + SWADDR(bRow0 + g * 16, ko + lmChunk));
                #pragma unroll
                for (int m = 0; m < 2; m++)
                    #pragma unroll
                    for (int ng = 0; ng < 4; ng++) {
                        const int g = ng >> 1, sub = ng & 1;
                        mma_f16(acc[m][ng], ah[m], bh[g][sub], bh[g][sub + 2]);
                    }
            }
        }
        CP_WAIT(0);   // drain before next tile reuses stages

        // ---- epilogue: acc + bias + scale * (Ares . loraB_fp16[a, o, :]) ----
        const int gID = lane >> 2, tig = lane & 3;
        #pragma unroll
        for (int m = 0; m < 2; m++) {
            #pragma unroll
            for (int h = 0; h < 2; h++) {
                const int rl = warpM * 32 + m * 16 + gID + h * 8;
                const int tok = tokSh[rl];
                const int a   = adSh[rl];
                const float sc = scSh[rl];
                const float* ar = &AresSh[rl][0];
                const float4 ar0 = *reinterpret_cast<const float4*>(ar + 0);
                const float4 ar1 = *reinterpret_cast<const float4*>(ar + 4);
                const float4 ar2 = *reinterpret_cast<const float4*>(ar + 8);
                const float4 ar3 = *reinterpret_cast<const float4*>(ar + 12);
                const __half* Bb = g_Bi + (size_t)a * D_OUT * RANK;
                float* orow = out + (size_t)tok * D_OUT + colBlock;

                #pragma unroll
                for (int ng = 0; ng < 4; ng++) {
                    const int c0 = warpN * 32 + ng * 8 + 2 * tig;
                    float r2[2];
                    #pragma unroll
                    for (int q = 0; q < 2; q++) {
                        const int o = colBlock + c0 + q;
                        const uint4* Bp = reinterpret_cast<const uint4*>(Bb + (size_t)o * RANK);
                        uint4 u0 = __ldg(Bp);
                        uint4 u1 = __ldg(Bp + 1);
                        float sdot = 0.f;
                        sdot = dot_h2(sdot, u0.x, ar0.x, ar0.y);
                        sdot = dot_h2(sdot, u0.y, ar0.z, ar0.w);
                        sdot = dot_h2(sdot, u0.z, ar1.x, ar1.y);
                        sdot = dot_h2(sdot, u0.w, ar1.z, ar1.w);
                        sdot = dot_h2(sdot, u1.x, ar2.x, ar2.y);
                        sdot = dot_h2(sdot, u1.y, ar2.z, ar2.w);
                        sdot = dot_h2(sdot, u1.z, ar3.x, ar3.y);
                        sdot = dot_h2(sdot, u1.w, ar3.z, ar3.w);
                        r2[q] = acc[m][ng][h * 2 + q] + __ldg(bias + o) + sc * sdot;
                    }
                    *reinterpret_cast<float2*>(orow + c0) = make_float2(r2[0], r2[1]);
                }
            }
        }
    }
}

// ---------------------------------------------------------------------------
// Launch
// ---------------------------------------------------------------------------
extern "C" void kernel_launch(void* const* d_in, const int* in_sizes, int n_in,
                              void* d_out, int out_size)
{
    const float* x           = (const float*)d_in[0];
    const int*   adapter_ids = (const int*)  d_in[1];
    const float* W_base      = (const float*)d_in[2];
    const float* b_base      = (const float*)d_in[3];
    const float* lora_A      = (const float*)d_in[4];
    const float* lora_B      = (const float*)d_in[5];
    const float* lora_scal   = (const float*)d_in[6];
    float*       out         = (float*)d_out;

    cudaFuncSetAttribute(gemm_mma_kernel,
                         cudaFuncAttributeMaxDynamicSharedMemorySize, DYN_BYTES);

    prepass_kernel<<<4097, 256>>>(x, W_base, lora_A, lora_B, adapter_ids);
    shrink_gemm_kernel<<<dim3(32, 4), 256>>>();
    gemm_mma_kernel<<<GRID_PERSIST, TPB, DYN_BYTES>>>(b_base, lora_scal, out);
}

// round 14
// speedup vs baseline: 1.0839x; 1.0839x over previous
#include <cuda_runtime.h>
#include <cuda_fp16.h>
#include <cstdint>

// ---------------- problem constants ----------------
#define N_TOK 4096
#define D_IN  2048
#define D_OUT 2048
#define RANK  16
#define MAX_LORAS 32

// ---------------- GEMM tiling (R12-proven: BN=128, warp tile 64x32) ----------
#define BM 128
#define BN 128
#define BK 64                 // fp16 elems per K-tile (128 bytes/row)
#define NKT (D_IN / BK)       // 32
#define TPB 256
#define STAGES 3
#define NTILES ((N_TOK / BM) * (D_OUT / BN))   // 512
#define GRID_PERSIST 304      // 2 CTAs/SM x 152 SMs (GB300)

#define ARR_BYTES (128 * 128)            // 16384 per tile array
#define STAGE_BYTES (2 * ARR_BYTES)      // A, B  (32768)
#define DYN_BYTES (STAGES * STAGE_BYTES) // 98304 -> 2 CTAs/SM

// XOR-SW128 swizzle: byte addr = row*128 + (col ^ ((row&7)<<4)), col in [0,128)
#define SWADDR(row, col) ((uint32_t)((row) * 128 + ((col) ^ (((row) & 7) << 4))))

// ---------------- device scratch (no runtime allocation allowed) ----------------
__device__ __align__(16) float  g_Ares[N_TOK * RANK];     // SORTED token order
__device__ __align__(16) __half g_Xi[N_TOK * D_IN];
__device__ __align__(16) __half g_Wi[D_OUT * D_IN];
__device__ __align__(16) __half g_Ai[MAX_LORAS * RANK * D_IN];
__device__ __align__(16) __half g_Bi[MAX_LORAS * D_OUT * RANK];
__device__ __align__(16) int    g_perm[N_TOK];            // sorted pos -> token
__device__ __align__(16) int    g_sortedAdp[N_TOK];       // sorted pos -> adapter
__device__ __align__(16) int    g_binStart[MAX_LORAS + 1];

// ---------------- PTX helpers (baseline-portable: sm_80-era ops) ----------------
__device__ __forceinline__ uint32_t smem_u32(const void* p) {
    uint32_t a;
    asm("{ .reg .u64 t; cvta.to.shared.u64 t, %1; cvt.u32.u64 %0, t; }" : "=r"(a) : "l"(p));
    return a;
}
#define CP16(dst, src) \
    asm volatile("cp.async.cg.shared.global [%0], [%1], 16;" :: "r"(dst), "l"(src) : "memory")
#define CP_COMMIT()  asm volatile("cp.async.commit_group;" ::: "memory")
#define CP_WAIT(n)   asm volatile("cp.async.wait_group %0;" :: "n"(n) : "memory")

__device__ __forceinline__ void ldsm4(uint32_t* r, uint32_t addr) {
    asm volatile("ldmatrix.sync.aligned.m8n8.x4.shared.b16 {%0,%1,%2,%3}, [%4];"
        : "=r"(r[0]), "=r"(r[1]), "=r"(r[2]), "=r"(r[3]) : "r"(addr));
}
__device__ __forceinline__ void mma_f16(float* d, const uint32_t* a,
                                        uint32_t b0, uint32_t b1) {
    asm volatile(
        "mma.sync.aligned.m16n8k16.row.col.f32.f16.f16.f32 "
        "{%0,%1,%2,%3}, {%4,%5,%6,%7}, {%8,%9}, {%0,%1,%2,%3};"
        : "+f"(d[0]), "+f"(d[1]), "+f"(d[2]), "+f"(d[3])
        : "r"(a[0]), "r"(a[1]), "r"(a[2]), "r"(a[3]), "r"(b0), "r"(b1));
}
__device__ __forceinline__ float dot_h2(float acc, uint32_t h2, float a0, float a1) {
    float2 f = __half22float2(*reinterpret_cast<__half2*>(&h2));
    return acc + a0 * f.x + a1 * f.y;
}
__device__ __forceinline__ uint2 f4_to_h4(float4 v) {
    __half2 p0 = __floats2half2_rn(v.x, v.y);
    __half2 p1 = __floats2half2_rn(v.z, v.w);
    uint2 u;
    u.x = *reinterpret_cast<uint32_t*>(&p0);
    u.y = *reinterpret_cast<uint32_t*>(&p1);
    return u;
}

// ---------------------------------------------------------------------------
// Kernel 1 (prepass, R13-proven):
//   block 0:             stable counting sort (concurrent with converts)
//   blocks [1, 2049):    X convert, 4 float4/thread (2M float4 total)
//   blocks [2049, 3073): W convert, 4 float4/thread (1M float4 total)
//   blocks [3073, 4097): loraA + loraB convert
// ---------------------------------------------------------------------------
__global__ __launch_bounds__(256) void prepass_kernel(
    const float* __restrict__ x, const float* __restrict__ w,
    const float* __restrict__ lora_A, const float* __restrict__ lora_B,
    const int* __restrict__ adapter_ids)
{
    const int bid = blockIdx.x;
    const int tid = threadIdx.x;

    if (bid == 0) {
        // ---- stable counting sort of 4096 tokens into 32 bins ----
        __shared__ uint32_t hist[256 * 33];   // padded stride (bank spread)
        __shared__ uint32_t binTotal[32];
        __shared__ uint32_t binBase[33];

        int ids[16];
        #pragma unroll
        for (int j = 0; j < 33; j++) hist[tid * 33 + j] = 0;
        __syncthreads();
        #pragma unroll
        for (int j = 0; j < 16; j++) {
            ids[j] = adapter_ids[tid * 16 + j];
            hist[tid * 33 + ids[j]]++;
        }
        __syncthreads();
        if (tid < 32) {        // per-bin prefix over threads (stable base)
            uint32_t s = 0;
            for (int t = 0; t < 256; t++) {
                uint32_t c = hist[t * 33 + tid];
                hist[t * 33 + tid] = s;
                s += c;
            }
            binTotal[tid] = s;
        }
        __syncthreads();
        if (tid == 0) {
            uint32_t acc = 0;
            for (int b = 0; b < 32; b++) { binBase[b] = acc; acc += binTotal[b]; }
            binBase[32] = acc;   // = 4096
        }
        __syncthreads();
        #pragma unroll
        for (int j = 0; j < 16; j++) {       // stable scatter
            const int b = ids[j];
            const uint32_t off = hist[tid * 33 + b]++;
            const uint32_t pos = binBase[b] + off;
            g_perm[pos]      = tid * 16 + j;
            g_sortedAdp[pos] = b;
        }
        if (tid < 33) g_binStart[tid] = (int)binBase[tid];
        return;
    }

    if (bid < 2049) {                                // X: 2048 blocks, 2M float4
        const int base = (bid - 1) * 1024 + tid;
        float4 v0 = reinterpret_cast<const float4*>(x)[base + 0 * 256];
        float4 v1 = reinterpret_cast<const float4*>(x)[base + 1 * 256];
        float4 v2 = reinterpret_cast<const float4*>(x)[base + 2 * 256];
        float4 v3 = reinterpret_cast<const float4*>(x)[base + 3 * 256];
        *reinterpret_cast<uint2*>(&g_Xi[(size_t)(base + 0 * 256) * 4]) = f4_to_h4(v0);
        *reinterpret_cast<uint2*>(&g_Xi[(size_t)(base + 1 * 256) * 4]) = f4_to_h4(v1);
        *reinterpret_cast<uint2*>(&g_Xi[(size_t)(base + 2 * 256) * 4]) = f4_to_h4(v2);
        *reinterpret_cast<uint2*>(&g_Xi[(size_t)(base + 3 * 256) * 4]) = f4_to_h4(v3);
        return;
    }
    if (bid < 3073) {                                // W: 1024 blocks, 1M float4
        const int base = (bid - 2049) * 1024 + tid;
        float4 v0 = reinterpret_cast<const float4*>(w)[base + 0 * 256];
        float4 v1 = reinterpret_cast<const float4*>(w)[base + 1 * 256];
        float4 v2 = reinterpret_cast<const float4*>(w)[base + 2 * 256];
        float4 v3 = reinterpret_cast<const float4*>(w)[base + 3 * 256];
        *reinterpret_cast<uint2*>(&g_Wi[(size_t)(base + 0 * 256) * 4]) = f4_to_h4(v0);
        *reinterpret_cast<uint2*>(&g_Wi[(size_t)(base + 1 * 256) * 4]) = f4_to_h4(v1);
        *reinterpret_cast<uint2*>(&g_Wi[(size_t)(base + 2 * 256) * 4]) = f4_to_h4(v2);
        *reinterpret_cast<uint2*>(&g_Wi[(size_t)(base + 3 * 256) * 4]) = f4_to_h4(v3);
        return;
    }
    {                                                // loraA/B: 262144 f4 each
        const int idx = (bid - 3073) * 256 + tid;
        float4 va = reinterpret_cast<const float4*>(lora_A)[idx];
        float4 vb = reinterpret_cast<const float4*>(lora_B)[idx];
        *reinterpret_cast<uint2*>(&g_Ai[(size_t)idx * 4]) = f4_to_h4(va);
        *reinterpret_cast<uint2*>(&g_Bi[(size_t)idx * 4]) = f4_to_h4(vb);
    }
}

// ---------------------------------------------------------------------------
// Kernel 2: shrink as per-adapter mma GEMM (unchanged — proven).
// ---------------------------------------------------------------------------
__global__ __launch_bounds__(256) void shrink_gemm_kernel()
{
    __shared__ __align__(16) char xs[2][16384];   // X tiles 128x64 fp16
    __shared__ __align__(16) char as_[2][2048];   // A tiles 16x64 fp16
    __shared__ int tokSh[128];

    const int a   = blockIdx.x;
    const int cy  = blockIdx.y;
    const int tid = threadIdx.x;
    const int wid = tid >> 5, lane = tid & 31;

    const int binS = g_binStart[a], binE = g_binStart[a + 1];
    const int base = binS + cy * 128;
    int cnt = binE - base;
    if (cnt <= 0) return;
    if (cnt > 128) cnt = 128;

    if (tid < 128) tokSh[tid] = g_perm[base + (tid < cnt ? tid : cnt - 1)];
    __syncthreads();

    const int ldCol = (tid & 7) * 16;
    auto load = [&](int kt, int stg) {
        #pragma unroll
        for (int i = 0; i < 4; i++) {
            const int c = tid + i * 256;          // 0..1023
            const int row = c >> 3;
            CP16(smem_u32(xs[stg]) + SWADDR(row, ldCol),
                 (const char*)g_Xi + (size_t)tokSh[row] * 4096 + kt * 128 + ldCol);
        }
        if (tid < 128) {
            const int row = tid >> 3;             // 0..15
            CP16(smem_u32(as_[stg]) + SWADDR(row, ldCol),
                 (const char*)g_Ai + ((size_t)a * RANK + row) * 4096 + kt * 128 + ldCol);
        }
        CP_COMMIT();
    };

    float acc2[2][4];
    #pragma unroll
    for (int i = 0; i < 2; i++)
        #pragma unroll
        for (int k = 0; k < 4; k++) acc2[i][k] = 0.f;

    const int lmRow = lane & 15, lmChunk = (lane >> 4) * 16;

    load(0, 0);
    for (int kt = 0; kt < NKT; kt++) {
        if (kt + 1 < NKT) load(kt + 1, (kt + 1) & 1); else CP_COMMIT();
        CP_WAIT(1);
        __syncthreads();
        const uint32_t xb = smem_u32(xs[kt & 1]);
        const uint32_t ab = smem_u32(as_[kt & 1]);
        #pragma unroll
        for (int s = 0; s < 4; s++) {
            uint32_t xh[4], bh[4];
            ldsm4(xh, xb + SWADDR(wid * 16 + lmRow, s * 32 + lmChunk));
            ldsm4(bh, ab + SWADDR(lmRow,           s * 32 + lmChunk));
            mma_f16(acc2[0], xh, bh[0], bh[2]);
            mma_f16(acc2[1], xh, bh[1], bh[3]);
        }
        __syncthreads();   // protect stage (kt+1)&1 reuse next iteration
    }

    const int gID = lane >> 2, tig = lane & 3;
    #pragma unroll
    for (int h = 0; h < 2; h++) {
        const int r = wid * 16 + gID + h * 8;
        if (r < cnt) {
            float* dst = g_Ares + (size_t)(base + r) * RANK;
            #pragma unroll
            for (int ng = 0; ng < 2; ng++) {
                const int c = ng * 8 + 2 * tig;
                *reinterpret_cast<float2*>(dst + c) =
                    make_float2(acc2[ng][h * 2], acc2[ng][h * 2 + 1]);
            }
        }
    }
}

// ---------------------------------------------------------------------------
// Kernel 3: persistent fp16 mma.sync GEMM over SORTED token rows + fused
// LoRA expand epilogue (R12-proven: BN=128, static schedule, warp 64x32).
// ---------------------------------------------------------------------------
__global__ __launch_bounds__(TPB, 2) void gemm_mma_kernel(
    const float* __restrict__ bias,
    const float* __restrict__ scaling,
    float*       __restrict__ out)
{
    extern __shared__ char dsm[];
    __shared__ __align__(16) float AresSh[BM][RANK];
    __shared__ int   adSh[BM];
    __shared__ float scSh[BM];
    __shared__ int   tokSh[BM];

    const int tid  = threadIdx.x;
    const int wid  = tid >> 5, lane = tid & 31;
    const int warpM = wid >> 2;          // 0..1 (64 rows)
    const int warpN = wid & 3;           // 0..3 (32 cols)

    const uint32_t dynb = smem_u32(dsm);
    const int lmRow   = lane & 15;
    const int lmChunk = (lane >> 4) * 16;
    const int aRow0 = warpM * 64 + lmRow;
    const int bRow0 = warpN * 32 + lmRow;
    const int ldCol = (tid & 7) * 16;

    for (unsigned int t = blockIdx.x; t < NTILES; t += gridDim.x) {
        // WAR guard: prior tile's epilogue reads of smem preload arrays
        __syncthreads();

        const int rowBlock = (int)(t >> 4) * BM;     // sorted-row block
        const int colBlock = (int)(t & 15) * BN;

        // preload: Ares rows (sorted-contiguous), adapters, scales, tokens
        {
            const float4* ag  = reinterpret_cast<const float4*>(g_Ares + (size_t)rowBlock * RANK);
            float4*       as4 = reinterpret_cast<float4*>(&AresSh[0][0]);
            as4[tid]       = ag[tid];
            as4[tid + 256] = ag[tid + 256];
            if (tid < BM) {
                const int sp = rowBlock + tid;
                const int a  = g_sortedAdp[sp];
                adSh[tid]  = a;
                scSh[tid]  = scaling[a];
                tokSh[tid] = g_perm[sp];
            }
        }
        __syncthreads();   // tokSh ready before gathered loads

        const char* srcW = (const char*)(g_Wi + (size_t)colBlock * D_IN);

        auto load_tile = [&](int kt, int stg) {
            const uint32_t sb = dynb + stg * STAGE_BYTES;
            const size_t koff = (size_t)kt * (BK * 2);   // 128 B per row
            #pragma unroll
            for (int i = 0; i < 4; i++) {
                const int c   = tid + i * 256;           // 0..1023
                const int row = c >> 3;
                const uint32_t d = SWADDR(row, ldCol);
                CP16(sb + 0 * ARR_BYTES + d,
                     (const char*)g_Xi + (size_t)tokSh[row] * (D_IN * 2) + koff + ldCol);
                CP16(sb + 1 * ARR_BYTES + d,
                     srcW + (size_t)row * (D_IN * 2) + koff + ldCol);
            }
            CP_COMMIT();
        };

        float acc[4][4][4];
        #pragma unroll
        for (int m = 0; m < 4; m++)
            #pragma unroll
            for (int n = 0; n < 4; n++)
                #pragma unroll
                for (int k = 0; k < 4; k++) acc[m][n][k] = 0.f;

        load_tile(0, 0);
        load_tile(1, 1);

        for (int kt = 0; kt < NKT; kt++) {
            const int stg = kt % STAGES;
            CP_WAIT(STAGES - 2);
            __syncthreads();
            if (kt + STAGES - 1 < NKT)
                load_tile(kt + STAGES - 1, (kt + STAGES - 1) % STAGES);
            else
                CP_COMMIT();   // empty group keeps wait accounting exact

            const uint32_t sb = dynb + stg * STAGE_BYTES;
            const uint32_t aArr = sb + 0 * ARR_BYTES;
            const uint32_t bArr = sb + 1 * ARR_BYTES;

            #pragma unroll
            for (int s = 0; s < 4; s++) {
                const int ko = s * 32;
                uint32_t ah[4][4], bh[2][4];
                #pragma unroll
                for (int m = 0; m < 4; m++)
                    ldsm4(ah[m], aArr + SWADDR(aRow0 + m * 16, ko + lmChunk));
                #pragma unroll
                for (int g = 0; g < 2; g++)
                    ldsm4(bh[g], bArr + SWADDR(bRow0 + g * 16, ko + lmChunk));
                #pragma unroll
                for (int m = 0; m < 4; m++)
                    #pragma unroll
                    for (int ng = 0; ng < 4; ng++) {
                        const int g = ng >> 1, sub = ng & 1;
                        mma_f16(acc[m][ng], ah[m], bh[g][sub], bh[g][sub + 2]);
                    }
            }
        }
        CP_WAIT(0);   // drain before next tile reuses stages

        // ---- epilogue: acc + bias + scale * (Ares . loraB_fp16[a, o, :]) ----
        const int gID = lane >> 2, tig = lane & 3;
        #pragma unroll
        for (int m = 0; m < 4; m++) {
            #pragma unroll
            for (int h = 0; h < 2; h++) {
                const int rl = warpM * 64 + m * 16 + gID + h * 8;
                const int tok = tokSh[rl];
                const int a   = adSh[rl];
                const float sc = scSh[rl];
                const float* ar = &AresSh[rl][0];
                const float4 ar0 = *reinterpret_cast<const float4*>(ar + 0);
                const float4 ar1 = *reinterpret_cast<const float4*>(ar + 4);
                const float4 ar2 = *reinterpret_cast<const float4*>(ar + 8);
                const float4 ar3 = *reinterpret_cast<const float4*>(ar + 12);
                const __half* Bb = g_Bi + (size_t)a * D_OUT * RANK;
                float* orow = out + (size_t)tok * D_OUT + colBlock;

                #pragma unroll
                for (int ng = 0; ng < 4; ng++) {
                    const int c0 = warpN * 32 + ng * 8 + 2 * tig;
                    float r2[2];
                    #pragma unroll
                    for (int q = 0; q < 2; q++) {
                        const int o = colBlock + c0 + q;
                        const uint4* Bp = reinterpret_cast<const uint4*>(Bb + (size_t)o * RANK);
                        uint4 u0 = __ldg(Bp);
                        uint4 u1 = __ldg(Bp + 1);
                        float sdot = 0.f;
                        sdot = dot_h2(sdot, u0.x, ar0.x, ar0.y);
                        sdot = dot_h2(sdot, u0.y, ar0.z, ar0.w);
                        sdot = dot_h2(sdot, u0.z, ar1.x, ar1.y);
                        sdot = dot_h2(sdot, u0.w, ar1.z, ar1.w);
                        sdot = dot_h2(sdot, u1.x, ar2.x, ar2.y);
                        sdot = dot_h2(sdot, u1.y, ar2.z, ar2.w);
                        sdot = dot_h2(sdot, u1.z, ar3.x, ar3.y);
                        sdot = dot_h2(sdot, u1.w, ar3.z, ar3.w);
                        r2[q] = acc[m][ng][h * 2 + q] + __ldg(bias + o) + sc * sdot;
                    }
                    *reinterpret_cast<float2*>(orow + c0) = make_float2(r2[0], r2[1]);
                }
            }
        }
    }
}

// ---------------------------------------------------------------------------
// Launch
// ---------------------------------------------------------------------------
extern "C" void kernel_launch(void* const* d_in, const int* in_sizes, int n_in,
                              void* d_out, int out_size)
{
    const float* x           = (const float*)d_in[0];
    const int*   adapter_ids = (const int*)  d_in[1];
    const float* W_base      = (const float*)d_in[2];
    const float* b_base      = (const float*)d_in[3];
    const float* lora_A      = (const float*)d_in[4];
    const float* lora_B      = (const float*)d_in[5];
    const float* lora_scal   = (const float*)d_in[6];
    float*       out         = (float*)d_out;

    cudaFuncSetAttribute(gemm_mma_kernel,
                         cudaFuncAttributeMaxDynamicSharedMemorySize, DYN_BYTES);

    prepass_kernel<<<4097, 256>>>(x, W_base, lora_A, lora_B, adapter_ids);
    shrink_gemm_kernel<<<dim3(32, 4), 256>>>();
    gemm_mma_kernel<<<GRID_PERSIST, TPB, DYN_BYTES>>>(b_base, lora_scal, out);
}